// round 15
// baseline (speedup 1.0000x reference)
#include <cuda_runtime.h>
#include <cuda_fp16.h>
#include <cstdint>
#include <cstdio>

// Problem dims (fixed): T=2048, B=8, D=1024
#define TT 2048
#define BB 8
#define DD 1024
#define MROWS (TT*BB)          // 16384

// ---------------------------------------------------------------------------
// Scratch (device globals; no allocation allowed)
// ---------------------------------------------------------------------------
__device__ __half g_h  [(size_t)MROWS * DD];          // layernorm(data), fp16
__device__ __half g_qx [(size_t)MROWS * DD];          // q only, fp16
__device__ __half g_W  [(size_t)TT * TT];             // exp(pos_bias), fp16
__device__ __half g_XT [(size_t)2 * BB * DD * TT];    // row 2n = ek*v, 2n+1 = ek (n=b*D+d)
__device__ __half g_ag [(size_t)MROWS * 2 * DD];      // [act | gate-ffn] per row (K=2048)
__device__ __half g_w12[(size_t)5*DD*DD];             // [q ; interleaved k/v ; interleaved x1/gate]
__device__ __half g_w34[(size_t)DD*2*DD];             // row n = [out_w[n] | fc2_w[n]]
__device__ float  g_b12[(size_t)5*DD];                // matching interleaved biases
__device__ float  g_b34[(size_t)DD];

// ---------------------------------------------------------------------------
// Helpers
// ---------------------------------------------------------------------------
__device__ __forceinline__ void cp_async16(uint32_t saddr, const void* gptr) {
    asm volatile("cp.async.cg.shared.global [%0], [%1], 16;\n" :: "r"(saddr), "l"(gptr));
}
__device__ __forceinline__ void cp_commit() {
    asm volatile("cp.async.commit_group;\n");
}
__device__ __forceinline__ void ldsm_x4(uint32_t& r0, uint32_t& r1, uint32_t& r2, uint32_t& r3,
                                        uint32_t addr) {
    asm volatile("ldmatrix.sync.aligned.m8n8.x4.shared.b16 {%0,%1,%2,%3}, [%4];"
                 : "=r"(r0), "=r"(r1), "=r"(r2), "=r"(r3) : "r"(addr));
}

// ---------------------------------------------------------------------------
// Fused layernorm + prep kernel (block-range dispatch).
// ---------------------------------------------------------------------------
#define P0_END (DD*DD)                   // w12 q rows (straight copy)
#define P1_END (P0_END + DD*DD)          // w12 k/v interleave
#define P2_END (P1_END + DD*DD)          // w12 x1/gate interleave
#define P3_END (P2_END + DD*DD)          // w34
#define P4_END (P3_END + TT*TT)          // expw
#define P5_END (P4_END + 4096)           // biases

__global__ void lnprep_k(const float* __restrict__ data, __half* __restrict__ h,
                         const float* __restrict__ qkv_w, const float* __restrict__ fc1_w,
                         const float* __restrict__ out_w, const float* __restrict__ fc2_w,
                         const float* __restrict__ qkv_b, const float* __restrict__ fc1_b,
                         const float* __restrict__ out_b, const float* __restrict__ fc2_b,
                         const float* __restrict__ pos_b,
                         __half* __restrict__ w12, __half* __restrict__ w34,
                         __half* __restrict__ W,
                         float* __restrict__ b12, float* __restrict__ b34) {
    if (blockIdx.x < MROWS) {
        __shared__ float red[16];
        const size_t row = blockIdx.x;
        const float4* xr = (const float4*)(data + row * DD);
        float4 v = xr[threadIdx.x];
        float s = v.x + v.y + v.z + v.w;
        float q = v.x*v.x + v.y*v.y + v.z*v.z + v.w*v.w;
        #pragma unroll
        for (int o = 16; o; o >>= 1) {
            s += __shfl_xor_sync(0xffffffffu, s, o);
            q += __shfl_xor_sync(0xffffffffu, q, o);
        }
        int wid = threadIdx.x >> 5;
        if ((threadIdx.x & 31) == 0) { red[wid] = s; red[8 + wid] = q; }
        __syncthreads();
        s = 0.f; q = 0.f;
        #pragma unroll
        for (int i = 0; i < 8; i++) { s += red[i]; q += red[8 + i]; }
        float mean = s * (1.0f / DD);
        float var  = fmaxf(q * (1.0f / DD) - mean * mean, 0.0f);
        float rs   = rsqrtf(var + 1.17549435e-38f);
        __half2* hr = (__half2*)(h + row * DD);
        hr[2*threadIdx.x]     = __floats2half2_rn((v.x - mean) * rs, (v.y - mean) * rs);
        hr[2*threadIdx.x + 1] = __floats2half2_rn((v.z - mean) * rs, (v.w - mean) * rs);
        return;
    }
    int i = (blockIdx.x - MROWS) * blockDim.x + threadIdx.x;
    if (i < P0_END) {
        w12[i] = __float2half_rn(qkv_w[i]);
    } else if (i < P1_END) {
        int i2 = i - P0_END;
        int d = i2 >> 10, c = i2 & 1023;
        size_t base = ((size_t)DD + 2 * d) * DD;
        w12[base + c]      = __float2half_rn(qkv_w[(size_t)(DD + d) * DD + c]);     // k_d
        w12[base + DD + c] = __float2half_rn(qkv_w[(size_t)(2 * DD + d) * DD + c]); // v_d
    } else if (i < P2_END) {
        int i2 = i - P1_END;
        int d = i2 >> 10, c = i2 & 1023;
        size_t base = ((size_t)3 * DD + 2 * d) * DD;
        w12[base + c]      = __float2half_rn(fc1_w[(size_t)d * DD + c]);            // x1_d
        w12[base + DD + c] = __float2half_rn(fc1_w[(size_t)(DD + d) * DD + c]);     // gate_d
    } else if (i < P3_END) {
        int i2 = i - P2_END;
        int n = i2 >> 10, c = i2 & 1023;
        w34[(size_t)n * 2048 + c]        = __float2half_rn(out_w[i2]);
        w34[(size_t)n * 2048 + 1024 + c] = __float2half_rn(fc2_w[i2]);
    } else if (i < P4_END) {
        int i2 = i - P3_END;
        W[i2] = __float2half_rn(expf(pos_b[i2]));
    } else if (i < P5_END) {
        int i2 = i - P4_END;
        if (i2 < DD) {
            b12[i2] = qkv_b[i2];
            b34[i2] = out_b[i2] + fc2_b[i2];
        } else if (i2 < 2 * DD) {
            int d = i2 - DD;
            b12[DD + 2 * d]     = qkv_b[DD + d];
            b12[DD + 2 * d + 1] = qkv_b[2 * DD + d];
        } else if (i2 < 3 * DD) {
            int d = i2 - 2 * DD;
            b12[3 * DD + 2 * d]     = fc1_b[d];
            b12[3 * DD + 2 * d + 1] = fc1_b[DD + d];
        }
    }
}

// ---------------------------------------------------------------------------
// GEMM tile config
// fp16 mma.sync m16n8k16 (fp32 accum), 128x256x64 block tile, 8 warps (64x64
// warp tiles), cp.async 3-stage pipeline, XOR-swizzled smem rows (128 B).
// ---------------------------------------------------------------------------
#define BM 128
#define BN 256
#define BK 64                                   // halves per k-tile
#define STAGES 3
#define A_TILE_BYTES 16384                      // 128 rows * 128 B
#define B_TILE_BYTES 32768                      // 256 rows * 128 B
#define STAGE_BYTES  49152                      // A + B
#define SMEM_BYTES (STAGES * STAGE_BYTES)       // 147,456 B -> 1 CTA/SM

// Mainloop shared by all GEMMs (accumulates c[4][8][4])
#define GEMM_MAINLOOP(Aptr, Bptr, Kdim)                                              \
    const int lr = tid >> 3;                                                          \
    const int lc = tid & 7;                                                           \
    const int scw = lc ^ (lr & 7);                                                    \
    const __half* gA = (Aptr) + (m0 + lr) * (size_t)(Kdim) + lc * 8;                  \
    const __half* gB = (Bptr) + (n0 + lr) * (size_t)(Kdim) + lc * 8;                  \
    const uint32_t sAa = smBase + (lr * 64 + scw * 8) * 2;                            \
    const uint32_t sBa = sAa + A_TILE_BYTES;                                          \
    const uint32_t rm  = lane & 7;                                                    \
    const uint32_t chA = lane >> 4;                                                   \
    const uint32_t chB = (lane >> 3) & 1;                                             \
    uint32_t aOff[4], bOff[4];                                                        \
    _Pragma("unroll")                                                                 \
    for (int mt = 0; mt < 4; mt++)                                                    \
        aOff[mt] = (wm + mt * 16 + (lane & 15)) * 128;                                \
    _Pragma("unroll")                                                                 \
    for (int p = 0; p < 4; p++)                                                       \
        bOff[p] = (wn + 16 * p + 8 * (lane >> 4) + (lane & 7)) * 128;                 \
    const int nk = (Kdim) / BK;                                                       \
    _Pragma("unroll")                                                                 \
    for (int st = 0; st < STAGES - 1; st++) {                                         \
        const uint32_t da = sAa + st * STAGE_BYTES;                                   \
        const uint32_t db = sBa + st * STAGE_BYTES;                                   \
        const size_t ko = (size_t)st * BK;                                            \
        _Pragma("unroll")                                                             \
        for (int i = 0; i < 4; i++)                                                   \
            cp_async16(da + i * 4096, gA + ko + (size_t)(32 * i) * (Kdim));           \
        _Pragma("unroll")                                                             \
        for (int i = 0; i < 8; i++)                                                   \
            cp_async16(db + i * 4096, gB + ko + (size_t)(32 * i) * (Kdim));           \
        cp_commit();                                                                  \
    }                                                                                 \
    int slot = 0, wslot = STAGES - 1;                                                 \
    for (int kt = 0; kt < nk; kt++) {                                                 \
        asm volatile("cp.async.wait_group %0;\n" :: "n"(STAGES - 2) : "memory");      \
        __syncthreads();                                                              \
        if (kt + STAGES - 1 < nk) {                                                   \
            const uint32_t da = sAa + wslot * STAGE_BYTES;                            \
            const uint32_t db = sBa + wslot * STAGE_BYTES;                            \
            const size_t ko = (size_t)(kt + STAGES - 1) * BK;                         \
            _Pragma("unroll")                                                         \
            for (int i = 0; i < 4; i++)                                               \
                cp_async16(da + i * 4096, gA + ko + (size_t)(32 * i) * (Kdim));       \
            _Pragma("unroll")                                                         \
            for (int i = 0; i < 8; i++)                                               \
                cp_async16(db + i * 4096, gB + ko + (size_t)(32 * i) * (Kdim));       \
        }                                                                             \
        cp_commit();                                                                  \
        const uint32_t aTile = smBase + slot * STAGE_BYTES;                           \
        const uint32_t bTile = aTile + A_TILE_BYTES;                                  \
        _Pragma("unroll")                                                             \
        for (int ks = 0; ks < 4; ks++) {                                              \
            const uint32_t swA = ((chA + 2 * ks) ^ rm) << 4;                          \
            const uint32_t swB = ((chB + 2 * ks) ^ rm) << 4;                          \
            uint32_t af[4][4], bf[8][2];                                              \
            _Pragma("unroll")                                                         \
            for (int mt = 0; mt < 4; mt++)                                            \
                ldsm_x4(af[mt][0], af[mt][1], af[mt][2], af[mt][3],                   \
                        aTile + aOff[mt] + swA);                                      \
            _Pragma("unroll")                                                         \
            for (int p = 0; p < 4; p++)                                               \
                ldsm_x4(bf[2*p][0], bf[2*p][1], bf[2*p+1][0], bf[2*p+1][1],           \
                        bTile + bOff[p] + swB);                                       \
            _Pragma("unroll")                                                         \
            for (int mt = 0; mt < 4; mt++)                                            \
                _Pragma("unroll")                                                     \
                for (int nt = 0; nt < 8; nt++) {                                      \
                    asm volatile(                                                     \
                        "mma.sync.aligned.m16n8k16.row.col.f32.f16.f16.f32 "          \
                        "{%0,%1,%2,%3}, {%4,%5,%6,%7}, {%8,%9}, {%0,%1,%2,%3};\n"     \
                        : "+f"(c[mt][nt][0]), "+f"(c[mt][nt][1]),                     \
                          "+f"(c[mt][nt][2]), "+f"(c[mt][nt][3])                      \
                        : "r"(af[mt][0]), "r"(af[mt][1]),                             \
                          "r"(af[mt][2]), "r"(af[mt][3]),                             \
                          "r"(bf[nt][0]), "r"(bf[nt][1]));                            \
                }                                                                     \
        }                                                                             \
        slot  = (slot  == STAGES - 1) ? 0 : slot + 1;                                 \
        wslot = (wslot == STAGES - 1) ? 0 : wslot + 1;                                \
    }

// Projection GEMM: A = h [16384,1024], B = w12 [5120,1024].
//  n0 <  1024: qx = q (+bias)
//  n0 <  3072: interleaved (k,v) pairs -> fused exp + smem transpose -> XT
//  else      : interleaved (x1,gate)   -> fused SwiGLU -> ag[:,1024:2048]
__global__ void __launch_bounds__(256) gemm_qkv(
    const __half* __restrict__ A, const __half* __restrict__ B,
    const float* __restrict__ bias,
    __half* __restrict__ qx, __half* __restrict__ XT, __half* __restrict__ ag)
{
    extern __shared__ __half sm[];
    const uint32_t smBase = (uint32_t)__cvta_generic_to_shared(sm);
    const int tid = threadIdx.x;
    const size_t m0 = (size_t)blockIdx.y * BM;
    const size_t n0 = (size_t)blockIdx.x * BN;
    const int warp = tid >> 5, lane = tid & 31;
    const int g = lane >> 2, tg = lane & 3;
    const int wm = (warp >> 2) * 64;
    const int wn = (warp & 3) * 64;

    float c[4][8][4];
    #pragma unroll
    for (int i = 0; i < 4; i++)
        #pragma unroll
        for (int j = 0; j < 8; j++)
            #pragma unroll
            for (int e = 0; e < 4; e++) c[i][j][e] = 0.0f;

    GEMM_MAINLOOP(A, B, DD)

    if (n0 < DD) {
        // ---- q epilogue -> qx [MROWS, DD] ----
        #pragma unroll
        for (int mt = 0; mt < 4; mt++) {
            const size_t r0 = m0 + wm + mt * 16 + g;
            const size_t r1 = r0 + 8;
            #pragma unroll
            for (int nt = 0; nt < 8; nt++) {
                const size_t col = n0 + wn + nt * 8 + tg * 2;
                const float b0 = bias[col], b1 = bias[col + 1];
                *(__half2*)(qx + r0 * DD + col) =
                    __floats2half2_rn(c[mt][nt][0] + b0, c[mt][nt][1] + b1);
                *(__half2*)(qx + r1 * DD + col) =
                    __floats2half2_rn(c[mt][nt][2] + b0, c[mt][nt][3] + b1);
            }
        }
    } else if (n0 < 3 * DD) {
        // ---- k/v epilogue: exp + transpose -> XT ----
        // CTA covers t in [t0, t0+16), all 8 b, d in [d0, d0+128).
        __syncthreads();   // stage buffers dead; reuse smem for transpose
        __half* sekv = sm;                 // 1024 chunks * 16 halves = 32 KB
        __half* sek  = sm + 16384;         // another 32 KB
        #pragma unroll
        for (int nt = 0; nt < 8; nt++) {
            const int collocal = wn + nt * 8 + tg * 2;
            const int dl = collocal >> 1;
            const size_t col = n0 + collocal;
            const float bk = bias[col], bv = bias[col + 1];
            uint32_t pkv[4], pke[4];
            #pragma unroll
            for (int mt = 0; mt < 4; mt++) {
                float k0 = c[mt][nt][0] + bk, v0 = c[mt][nt][1] + bv;
                float k1 = c[mt][nt][2] + bk, v1 = c[mt][nt][3] + bv;
                float e0 = expf(k0), e1 = expf(k1);
                __half2 hv = __floats2half2_rn(e0 * v0, e1 * v1);
                __half2 he = __floats2half2_rn(e0, e1);
                pkv[mt] = *(uint32_t*)&hv;
                pke[mt] = *(uint32_t*)&he;
            }
            const int chunk = dl * 8 + g;           // b = g
            const int toff  = (wm >> 3);            // 0 or 8
            *(uint4*)(sekv + chunk * 16 + toff) = make_uint4(pkv[0], pkv[1], pkv[2], pkv[3]);
            *(uint4*)(sek  + chunk * 16 + toff) = make_uint4(pke[0], pke[1], pke[2], pke[3]);
        }
        __syncthreads();
        const int t0 = (int)(m0 >> 3);
        const int d0 = (int)((n0 - DD) >> 1);
        #pragma unroll
        for (int i = 0; i < 8; i++) {
            const int cid = tid + 256 * i;          // [0, 2048)
            const int s = cid >> 10;                // 0 = ekv, 1 = ek
            const int rowid = cid & 1023;           // = dl*8 + b
            const int dl = rowid >> 3, b = rowid & 7;
            const __half* src = (s ? sek : sekv) + rowid * 16;
            const size_t xrow = 2 * ((size_t)b * DD + d0 + dl) + s;
            uint4* dst = (uint4*)(XT + xrow * TT + t0);
            dst[0] = ((const uint4*)src)[0];
            dst[1] = ((const uint4*)src)[1];
        }
    } else {
        // ---- fused SwiGLU epilogue -> ag[:, 1024 + d] ----
        #pragma unroll
        for (int mt = 0; mt < 4; mt++) {
            const size_t r0 = m0 + wm + mt * 16 + g;
            const size_t r1 = r0 + 8;
            #pragma unroll
            for (int nt = 0; nt < 8; nt++) {
                const size_t col = n0 + wn + nt * 8 + tg * 2;
                const float b0 = bias[col], b1 = bias[col + 1];
                const int d = (int)((col - 3 * DD) >> 1);
                float x1a = c[mt][nt][0] + b0, gta = c[mt][nt][1] + b1;
                float x1b = c[mt][nt][2] + b0, gtb = c[mt][nt][3] + b1;
                float spa = (gta > 20.0f) ? gta : log1pf(expf(gta));
                float spb = (gtb > 20.0f) ? gtb : log1pf(expf(gtb));
                ag[r0 * (2 * DD) + DD + d] = __float2half_rn(x1a * gta * tanhf(spa));
                ag[r1 * (2 * DD) + DD + d] = __float2half_rn(x1b * gtb * tanhf(spb));
            }
        }
    }
}

// Y-GEMM with fused AFT activation epilogue.
// A = W [T,T], B = XT [16384, T] (row 2n = ekv, 2n+1 = ek).
// Grid: x = m (16), y = n (64).
__global__ void __launch_bounds__(256) gemm_aft(
    const __half* __restrict__ A, const __half* __restrict__ B,
    const __half* __restrict__ qx, __half* __restrict__ ag)
{
    extern __shared__ __half sm[];
    const uint32_t smBase = (uint32_t)__cvta_generic_to_shared(sm);
    const int tid = threadIdx.x;
    const size_t m0 = (size_t)blockIdx.x * BM;
    const size_t n0 = (size_t)blockIdx.y * BN;
    const int warp = tid >> 5, lane = tid & 31;
    const int g = lane >> 2, tg = lane & 3;
    const int wm = (warp >> 2) * 64;
    const int wn = (warp & 3) * 64;

    float c[4][8][4];
    #pragma unroll
    for (int i = 0; i < 4; i++)
        #pragma unroll
        for (int j = 0; j < 8; j++)
            #pragma unroll
            for (int e = 0; e < 4; e++) c[i][j][e] = 0.0f;

    GEMM_MAINLOOP(A, B, TT)

    #pragma unroll
    for (int mt = 0; mt < 4; mt++) {
        const size_t t0 = m0 + wm + mt * 16 + g;    // time index
        const size_t t1 = t0 + 8;
        #pragma unroll
        for (int nt = 0; nt < 8; nt++) {
            const int colpair = (int)((n0 + wn + nt * 8) >> 1) + tg;  // = b*1024 + d
            const int b = colpair >> 10, d = colpair & 1023;
            const size_t mrow0 = t0 * BB + b;
            const size_t mrow1 = t1 * BB + b;
            float q0 = __half2float(qx[mrow0 * DD + d]);
            float q1 = __half2float(qx[mrow1 * DD + d]);
            float s0 = 1.0f / (1.0f + expf(-q0));
            float s1 = 1.0f / (1.0f + expf(-q1));
            ag[mrow0 * (2 * DD) + d] =
                __float2half_rn(s0 * (c[mt][nt][0] / c[mt][nt][1]));
            ag[mrow1 * (2 * DD) + d] =
                __float2half_rn(s1 * (c[mt][nt][2] / c[mt][nt][3]));
        }
    }
}

// Final GEMM: out = data + ag @ w34^T + b34
__global__ void __launch_bounds__(256) gemm_out(
    const __half* __restrict__ A, const __half* __restrict__ B,
    const float* __restrict__ bias, const float* __restrict__ aux,
    float* __restrict__ C)
{
    extern __shared__ __half sm[];
    const uint32_t smBase = (uint32_t)__cvta_generic_to_shared(sm);
    const int tid = threadIdx.x;
    const size_t m0 = (size_t)blockIdx.y * BM;
    const size_t n0 = (size_t)blockIdx.x * BN;
    const int warp = tid >> 5, lane = tid & 31;
    const int g = lane >> 2, tg = lane & 3;
    const int wm = (warp >> 2) * 64;
    const int wn = (warp & 3) * 64;
    const int N = DD;

    float c[4][8][4];
    #pragma unroll
    for (int i = 0; i < 4; i++)
        #pragma unroll
        for (int j = 0; j < 8; j++)
            #pragma unroll
            for (int e = 0; e < 4; e++) c[i][j][e] = 0.0f;

    GEMM_MAINLOOP(A, B, 2 * DD)

    #pragma unroll
    for (int mt = 0; mt < 4; mt++) {
        const size_t r0 = m0 + wm + mt * 16 + g;
        const size_t r1 = r0 + 8;
        #pragma unroll
        for (int nt = 0; nt < 8; nt++) {
            const size_t col = n0 + wn + nt * 8 + tg * 2;
            const float b0 = bias[col], b1 = bias[col + 1];
            const size_t i0 = r0 * N + col;
            const size_t i1 = r1 * N + col;
            C[i0]     = c[mt][nt][0] + b0 + aux[i0];
            C[i0 + 1] = c[mt][nt][1] + b1 + aux[i0 + 1];
            C[i1]     = c[mt][nt][2] + b0 + aux[i1];
            C[i1 + 1] = c[mt][nt][3] + b1 + aux[i1 + 1];
        }
    }
}

// ---------------------------------------------------------------------------
// Host launch
// ---------------------------------------------------------------------------
extern "C" void kernel_launch(void* const* d_in, const int* in_sizes, int n_in,
                              void* d_out, int out_size) {
    const float* data  = (const float*)d_in[0];
    const float* qkv_w = (const float*)d_in[1];
    const float* qkv_b = (const float*)d_in[2];
    const float* pos_b = (const float*)d_in[3];
    const float* out_w = (const float*)d_in[4];
    const float* out_b = (const float*)d_in[5];
    const float* fc1_w = (const float*)d_in[6];
    const float* fc1_b = (const float*)d_in[7];
    const float* fc2_w = (const float*)d_in[8];
    const float* fc2_b = (const float*)d_in[9];
    float* out = (float*)d_out;

    __half *h, *qx, *W, *XT, *ag, *w12, *w34;
    float *b12, *b34;
    cudaGetSymbolAddress((void**)&h,   g_h);
    cudaGetSymbolAddress((void**)&qx,  g_qx);
    cudaGetSymbolAddress((void**)&W,   g_W);
    cudaGetSymbolAddress((void**)&XT,  g_XT);
    cudaGetSymbolAddress((void**)&ag,  g_ag);
    cudaGetSymbolAddress((void**)&w12, g_w12);
    cudaGetSymbolAddress((void**)&w34, g_w34);
    cudaGetSymbolAddress((void**)&b12, g_b12);
    cudaGetSymbolAddress((void**)&b34, g_b34);

    cudaFuncSetAttribute(gemm_qkv, cudaFuncAttributeMaxDynamicSharedMemorySize, SMEM_BYTES);
    cudaFuncSetAttribute(gemm_aft, cudaFuncAttributeMaxDynamicSharedMemorySize, SMEM_BYTES);
    cudaFuncSetAttribute(gemm_out, cudaFuncAttributeMaxDynamicSharedMemorySize, SMEM_BYTES);

    // fused layernorm + weight/bias/exp(pos_bias) prep (one launch)
    lnprep_k<<<MROWS + P5_END / 256, 256>>>(data, h,
                                            qkv_w, fc1_w, out_w, fc2_w,
                                            qkv_b, fc1_b, out_b, fc2_b, pos_b,
                                            w12, w34, W, b12, b34);

    // projection GEMM: q -> qx; (k,v) -> exp/transpose -> XT; (x1,gate) -> SwiGLU -> ag
    gemm_qkv<<<dim3(5*DD/BN, MROWS/BM), 256, SMEM_BYTES>>>(h, w12, b12, qx, XT, ag);

    // act half of ag: fused W@XT^T + sigmoid(q)*num/den  (grid: x=m, y=n)
    gemm_aft<<<dim3(TT/BM, 2*BB*DD/BN), 256, SMEM_BYTES>>>(W, XT, qx, ag);

    // out = data + ag @ w34^T + b34   (fused out-proj + fc2)
    gemm_out<<<dim3(DD/BN, MROWS/BM), 256, SMEM_BYTES>>>(ag, w34, b34, data, out);
}

// round 16
// speedup vs baseline: 1.1786x; 1.1786x over previous
#include <cuda_runtime.h>
#include <cuda_fp16.h>
#include <cstdint>
#include <cstdio>

// Problem dims (fixed): T=2048, B=8, D=1024
#define TT 2048
#define BB 8
#define DD 1024
#define MROWS (TT*BB)          // 16384

// ---------------------------------------------------------------------------
// Scratch (device globals; no allocation allowed)
// ---------------------------------------------------------------------------
__device__ __half g_h  [(size_t)MROWS * DD];          // layernorm(data), fp16
__device__ __half g_qx [(size_t)MROWS * DD];          // q only, fp16
__device__ __half g_W  [(size_t)TT * TT];             // exp(pos_bias), fp16
__device__ __half g_XT [(size_t)2 * BB * DD * TT];    // row 2n = ek*v, 2n+1 = ek (n=b*D+d)
__device__ __half g_ag [(size_t)MROWS * 2 * DD];      // [act | gate-ffn] per row (K=2048)
__device__ __half g_w12[(size_t)5*DD*DD];             // [q ; interleaved k/v ; interleaved x1/gate]
__device__ __half g_w34[(size_t)DD*2*DD];             // row n = [out_w[n] | fc2_w[n]]
__device__ float  g_b12[(size_t)5*DD];                // matching interleaved biases
__device__ float  g_b34[(size_t)DD];

// ---------------------------------------------------------------------------
// Helpers
// ---------------------------------------------------------------------------
__device__ __forceinline__ void cp_async16(uint32_t saddr, const void* gptr) {
    asm volatile("cp.async.cg.shared.global [%0], [%1], 16;\n" :: "r"(saddr), "l"(gptr));
}
__device__ __forceinline__ void cp_commit() {
    asm volatile("cp.async.commit_group;\n");
}
__device__ __forceinline__ void ldsm_x4(uint32_t& r0, uint32_t& r1, uint32_t& r2, uint32_t& r3,
                                        uint32_t addr) {
    asm volatile("ldmatrix.sync.aligned.m8n8.x4.shared.b16 {%0,%1,%2,%3}, [%4];"
                 : "=r"(r0), "=r"(r1), "=r"(r2), "=r"(r3) : "r"(addr));
}

// ---------------------------------------------------------------------------
// Fused layernorm + prep kernel (block-range dispatch).
// ---------------------------------------------------------------------------
#define P0_END (DD*DD)                   // w12 q rows (straight copy)
#define P1_END (P0_END + DD*DD)          // w12 k/v interleave
#define P2_END (P1_END + DD*DD)          // w12 x1/gate interleave
#define P3_END (P2_END + DD*DD)          // w34
#define P4_END (P3_END + TT*TT)          // expw
#define P5_END (P4_END + 4096)           // biases

__global__ void lnprep_k(const float* __restrict__ data, __half* __restrict__ h,
                         const float* __restrict__ qkv_w, const float* __restrict__ fc1_w,
                         const float* __restrict__ out_w, const float* __restrict__ fc2_w,
                         const float* __restrict__ qkv_b, const float* __restrict__ fc1_b,
                         const float* __restrict__ out_b, const float* __restrict__ fc2_b,
                         const float* __restrict__ pos_b,
                         __half* __restrict__ w12, __half* __restrict__ w34,
                         __half* __restrict__ W,
                         float* __restrict__ b12, float* __restrict__ b34) {
    if (blockIdx.x < MROWS) {
        __shared__ float red[16];
        const size_t row = blockIdx.x;
        const float4* xr = (const float4*)(data + row * DD);
        float4 v = xr[threadIdx.x];
        float s = v.x + v.y + v.z + v.w;
        float q = v.x*v.x + v.y*v.y + v.z*v.z + v.w*v.w;
        #pragma unroll
        for (int o = 16; o; o >>= 1) {
            s += __shfl_xor_sync(0xffffffffu, s, o);
            q += __shfl_xor_sync(0xffffffffu, q, o);
        }
        int wid = threadIdx.x >> 5;
        if ((threadIdx.x & 31) == 0) { red[wid] = s; red[8 + wid] = q; }
        __syncthreads();
        s = 0.f; q = 0.f;
        #pragma unroll
        for (int i = 0; i < 8; i++) { s += red[i]; q += red[8 + i]; }
        float mean = s * (1.0f / DD);
        float var  = fmaxf(q * (1.0f / DD) - mean * mean, 0.0f);
        float rs   = rsqrtf(var + 1.17549435e-38f);
        __half2* hr = (__half2*)(h + row * DD);
        hr[2*threadIdx.x]     = __floats2half2_rn((v.x - mean) * rs, (v.y - mean) * rs);
        hr[2*threadIdx.x + 1] = __floats2half2_rn((v.z - mean) * rs, (v.w - mean) * rs);
        return;
    }
    int i = (blockIdx.x - MROWS) * blockDim.x + threadIdx.x;
    if (i < P0_END) {
        w12[i] = __float2half_rn(qkv_w[i]);
    } else if (i < P1_END) {
        int i2 = i - P0_END;
        int d = i2 >> 10, c = i2 & 1023;
        size_t base = ((size_t)DD + 2 * d) * DD;
        w12[base + c]      = __float2half_rn(qkv_w[(size_t)(DD + d) * DD + c]);     // k_d
        w12[base + DD + c] = __float2half_rn(qkv_w[(size_t)(2 * DD + d) * DD + c]); // v_d
    } else if (i < P2_END) {
        int i2 = i - P1_END;
        int d = i2 >> 10, c = i2 & 1023;
        size_t base = ((size_t)3 * DD + 2 * d) * DD;
        w12[base + c]      = __float2half_rn(fc1_w[(size_t)d * DD + c]);            // x1_d
        w12[base + DD + c] = __float2half_rn(fc1_w[(size_t)(DD + d) * DD + c]);     // gate_d
    } else if (i < P3_END) {
        int i2 = i - P2_END;
        int n = i2 >> 10, c = i2 & 1023;
        w34[(size_t)n * 2048 + c]        = __float2half_rn(out_w[i2]);
        w34[(size_t)n * 2048 + 1024 + c] = __float2half_rn(fc2_w[i2]);
    } else if (i < P4_END) {
        int i2 = i - P3_END;
        W[i2] = __float2half_rn(expf(pos_b[i2]));
    } else if (i < P5_END) {
        int i2 = i - P4_END;
        if (i2 < DD) {
            b12[i2] = qkv_b[i2];
            b34[i2] = out_b[i2] + fc2_b[i2];
        } else if (i2 < 2 * DD) {
            int d = i2 - DD;
            b12[DD + 2 * d]     = qkv_b[DD + d];
            b12[DD + 2 * d + 1] = qkv_b[2 * DD + d];
        } else if (i2 < 3 * DD) {
            int d = i2 - 2 * DD;
            b12[3 * DD + 2 * d]     = fc1_b[d];
            b12[3 * DD + 2 * d + 1] = fc1_b[DD + d];
        }
    }
}

// ---------------------------------------------------------------------------
// GEMM tile config
// fp16 mma.sync m16n8k16 (fp32 accum), 128x128x64 block tile, 4 warps (2x2 of
// 64x64 warp tiles, 128 threads), cp.async 3-stage pipeline, XOR-swizzled smem
// rows (128 B). 96 KB smem -> 2 CTAs/SM; independent CTAs overlap barriers.
// ---------------------------------------------------------------------------
#define BM 128
#define BN 128
#define BK 64                                   // halves per k-tile
#define NTHREADS 128
#define STAGES 3
#define A_TILE_BYTES 16384                      // 128 rows * 128 B
#define STAGE_BYTES  32768                      // A + B
#define SMEM_BYTES (STAGES * STAGE_BYTES)       // 98,304 B

// Mainloop shared by all GEMMs (accumulates c[4][8][4])
#define GEMM_MAINLOOP(Aptr, Bptr, Kdim)                                              \
    const int lr = tid >> 3;                                                          \
    const int lc = tid & 7;                                                           \
    const int scw = lc ^ (lr & 7);                                                    \
    const __half* gA = (Aptr) + (m0 + lr) * (size_t)(Kdim) + lc * 8;                  \
    const __half* gB = (Bptr) + (n0 + lr) * (size_t)(Kdim) + lc * 8;                  \
    const uint32_t sAa = smBase + (lr * 64 + scw * 8) * 2;                            \
    const uint32_t sBa = sAa + A_TILE_BYTES;                                          \
    const uint32_t rm  = lane & 7;                                                    \
    const uint32_t chA = lane >> 4;                                                   \
    const uint32_t chB = (lane >> 3) & 1;                                             \
    uint32_t aOff[4], bOff[4];                                                        \
    _Pragma("unroll")                                                                 \
    for (int mt = 0; mt < 4; mt++)                                                    \
        aOff[mt] = (wm + mt * 16 + (lane & 15)) * 128;                                \
    _Pragma("unroll")                                                                 \
    for (int p = 0; p < 4; p++)                                                       \
        bOff[p] = (wn + 16 * p + 8 * (lane >> 4) + (lane & 7)) * 128;                 \
    const int nk = (Kdim) / BK;                                                       \
    _Pragma("unroll")                                                                 \
    for (int st = 0; st < STAGES - 1; st++) {                                         \
        const uint32_t da = sAa + st * STAGE_BYTES;                                   \
        const uint32_t db = sBa + st * STAGE_BYTES;                                   \
        const size_t ko = (size_t)st * BK;                                            \
        _Pragma("unroll")                                                             \
        for (int i = 0; i < 8; i++) {                                                 \
            cp_async16(da + i * 2048, gA + ko + (size_t)(16 * i) * (Kdim));           \
            cp_async16(db + i * 2048, gB + ko + (size_t)(16 * i) * (Kdim));           \
        }                                                                             \
        cp_commit();                                                                  \
    }                                                                                 \
    int slot = 0, wslot = STAGES - 1;                                                 \
    for (int kt = 0; kt < nk; kt++) {                                                 \
        asm volatile("cp.async.wait_group %0;\n" :: "n"(STAGES - 2) : "memory");      \
        __syncthreads();                                                              \
        if (kt + STAGES - 1 < nk) {                                                   \
            const uint32_t da = sAa + wslot * STAGE_BYTES;                            \
            const uint32_t db = sBa + wslot * STAGE_BYTES;                            \
            const size_t ko = (size_t)(kt + STAGES - 1) * BK;                         \
            _Pragma("unroll")                                                         \
            for (int i = 0; i < 8; i++) {                                             \
                cp_async16(da + i * 2048, gA + ko + (size_t)(16 * i) * (Kdim));       \
                cp_async16(db + i * 2048, gB + ko + (size_t)(16 * i) * (Kdim));       \
            }                                                                         \
        }                                                                             \
        cp_commit();                                                                  \
        const uint32_t aTile = smBase + slot * STAGE_BYTES;                           \
        const uint32_t bTile = aTile + A_TILE_BYTES;                                  \
        _Pragma("unroll")                                                             \
        for (int ks = 0; ks < 4; ks++) {                                              \
            const uint32_t swA = ((chA + 2 * ks) ^ rm) << 4;                          \
            const uint32_t swB = ((chB + 2 * ks) ^ rm) << 4;                          \
            uint32_t af[4][4], bf[8][2];                                              \
            _Pragma("unroll")                                                         \
            for (int mt = 0; mt < 4; mt++)                                            \
                ldsm_x4(af[mt][0], af[mt][1], af[mt][2], af[mt][3],                   \
                        aTile + aOff[mt] + swA);                                      \
            _Pragma("unroll")                                                         \
            for (int p = 0; p < 4; p++)                                               \
                ldsm_x4(bf[2*p][0], bf[2*p][1], bf[2*p+1][0], bf[2*p+1][1],           \
                        bTile + bOff[p] + swB);                                       \
            _Pragma("unroll")                                                         \
            for (int mt = 0; mt < 4; mt++)                                            \
                _Pragma("unroll")                                                     \
                for (int nt = 0; nt < 8; nt++) {                                      \
                    asm volatile(                                                     \
                        "mma.sync.aligned.m16n8k16.row.col.f32.f16.f16.f32 "          \
                        "{%0,%1,%2,%3}, {%4,%5,%6,%7}, {%8,%9}, {%0,%1,%2,%3};\n"     \
                        : "+f"(c[mt][nt][0]), "+f"(c[mt][nt][1]),                     \
                          "+f"(c[mt][nt][2]), "+f"(c[mt][nt][3])                      \
                        : "r"(af[mt][0]), "r"(af[mt][1]),                             \
                          "r"(af[mt][2]), "r"(af[mt][3]),                             \
                          "r"(bf[nt][0]), "r"(bf[nt][1]));                            \
                }                                                                     \
        }                                                                             \
        slot  = (slot  == STAGES - 1) ? 0 : slot + 1;                                 \
        wslot = (wslot == STAGES - 1) ? 0 : wslot + 1;                                \
    }

// Projection GEMM: A = h [16384,1024], B = w12 [5120,1024].
//  n0 <  1024: qx = q (+bias)
//  n0 <  3072: interleaved (k,v) pairs -> fused exp + smem transpose -> XT
//  else      : interleaved (x1,gate)   -> fused SwiGLU -> ag[:,1024:2048]
__global__ void __launch_bounds__(NTHREADS, 2) gemm_qkv(
    const __half* __restrict__ A, const __half* __restrict__ B,
    const float* __restrict__ bias,
    __half* __restrict__ qx, __half* __restrict__ XT, __half* __restrict__ ag)
{
    extern __shared__ __half sm[];
    const uint32_t smBase = (uint32_t)__cvta_generic_to_shared(sm);
    const int tid = threadIdx.x;
    const size_t m0 = (size_t)blockIdx.y * BM;
    const size_t n0 = (size_t)blockIdx.x * BN;
    const int warp = tid >> 5, lane = tid & 31;
    const int g = lane >> 2, tg = lane & 3;
    const int wm = (warp >> 1) * 64;
    const int wn = (warp & 1) * 64;

    float c[4][8][4];
    #pragma unroll
    for (int i = 0; i < 4; i++)
        #pragma unroll
        for (int j = 0; j < 8; j++)
            #pragma unroll
            for (int e = 0; e < 4; e++) c[i][j][e] = 0.0f;

    GEMM_MAINLOOP(A, B, DD)

    if (n0 < DD) {
        // ---- q epilogue -> qx [MROWS, DD] ----
        #pragma unroll
        for (int mt = 0; mt < 4; mt++) {
            const size_t r0 = m0 + wm + mt * 16 + g;
            const size_t r1 = r0 + 8;
            #pragma unroll
            for (int nt = 0; nt < 8; nt++) {
                const size_t col = n0 + wn + nt * 8 + tg * 2;
                const float b0 = bias[col], b1 = bias[col + 1];
                *(__half2*)(qx + r0 * DD + col) =
                    __floats2half2_rn(c[mt][nt][0] + b0, c[mt][nt][1] + b1);
                *(__half2*)(qx + r1 * DD + col) =
                    __floats2half2_rn(c[mt][nt][2] + b0, c[mt][nt][3] + b1);
            }
        }
    } else if (n0 < 3 * DD) {
        // ---- k/v epilogue: exp + transpose -> XT ----
        // CTA covers t in [t0, t0+16), all 8 b, d in [d0, d0+64).
        __syncthreads();   // stage buffers dead; reuse smem for transpose
        __half* sekv = sm;                 // 512 chunks * 16 halves = 16 KB
        __half* sek  = sm + 8192;          // another 16 KB
        #pragma unroll
        for (int nt = 0; nt < 8; nt++) {
            const int collocal = wn + nt * 8 + tg * 2;
            const int dl = collocal >> 1;
            const size_t col = n0 + collocal;
            const float bk = bias[col], bv = bias[col + 1];
            uint32_t pkv[4], pke[4];
            #pragma unroll
            for (int mt = 0; mt < 4; mt++) {
                float k0 = c[mt][nt][0] + bk, v0 = c[mt][nt][1] + bv;
                float k1 = c[mt][nt][2] + bk, v1 = c[mt][nt][3] + bv;
                float e0 = expf(k0), e1 = expf(k1);
                __half2 hv = __floats2half2_rn(e0 * v0, e1 * v1);
                __half2 he = __floats2half2_rn(e0, e1);
                pkv[mt] = *(uint32_t*)&hv;
                pke[mt] = *(uint32_t*)&he;
            }
            const int chunk = dl * 8 + g;           // b = g
            const int toff  = (wm >> 3);            // 0 or 8
            *(uint4*)(sekv + chunk * 16 + toff) = make_uint4(pkv[0], pkv[1], pkv[2], pkv[3]);
            *(uint4*)(sek  + chunk * 16 + toff) = make_uint4(pke[0], pke[1], pke[2], pke[3]);
        }
        __syncthreads();
        const int t0 = (int)(m0 >> 3);
        const int d0 = (int)((n0 - DD) >> 1);
        #pragma unroll
        for (int i = 0; i < 8; i++) {
            const int cid = tid + NTHREADS * i;     // [0, 1024)
            const int s = cid >> 9;                 // 0 = ekv, 1 = ek
            const int rowid = cid & 511;            // = dl*8 + b
            const int dl = rowid >> 3, b = rowid & 7;
            const __half* src = (s ? sek : sekv) + rowid * 16;
            const size_t xrow = 2 * ((size_t)b * DD + d0 + dl) + s;
            uint4* dst = (uint4*)(XT + xrow * TT + t0);
            dst[0] = ((const uint4*)src)[0];
            dst[1] = ((const uint4*)src)[1];
        }
    } else {
        // ---- fused SwiGLU epilogue -> ag[:, 1024 + d] ----
        #pragma unroll
        for (int mt = 0; mt < 4; mt++) {
            const size_t r0 = m0 + wm + mt * 16 + g;
            const size_t r1 = r0 + 8;
            #pragma unroll
            for (int nt = 0; nt < 8; nt++) {
                const size_t col = n0 + wn + nt * 8 + tg * 2;
                const float b0 = bias[col], b1 = bias[col + 1];
                const int d = (int)((col - 3 * DD) >> 1);
                float x1a = c[mt][nt][0] + b0, gta = c[mt][nt][1] + b1;
                float x1b = c[mt][nt][2] + b0, gtb = c[mt][nt][3] + b1;
                float spa = (gta > 20.0f) ? gta : log1pf(expf(gta));
                float spb = (gtb > 20.0f) ? gtb : log1pf(expf(gtb));
                ag[r0 * (2 * DD) + DD + d] = __float2half_rn(x1a * gta * tanhf(spa));
                ag[r1 * (2 * DD) + DD + d] = __float2half_rn(x1b * gtb * tanhf(spb));
            }
        }
    }
}

// Y-GEMM with fused AFT activation epilogue.
// A = W [T,T], B = XT [16384, T] (row 2n = ekv, 2n+1 = ek).
// Grid: x = m (16), y = n (128).
__global__ void __launch_bounds__(NTHREADS, 2) gemm_aft(
    const __half* __restrict__ A, const __half* __restrict__ B,
    const __half* __restrict__ qx, __half* __restrict__ ag)
{
    extern __shared__ __half sm[];
    const uint32_t smBase = (uint32_t)__cvta_generic_to_shared(sm);
    const int tid = threadIdx.x;
    const size_t m0 = (size_t)blockIdx.x * BM;
    const size_t n0 = (size_t)blockIdx.y * BN;
    const int warp = tid >> 5, lane = tid & 31;
    const int g = lane >> 2, tg = lane & 3;
    const int wm = (warp >> 1) * 64;
    const int wn = (warp & 1) * 64;

    float c[4][8][4];
    #pragma unroll
    for (int i = 0; i < 4; i++)
        #pragma unroll
        for (int j = 0; j < 8; j++)
            #pragma unroll
            for (int e = 0; e < 4; e++) c[i][j][e] = 0.0f;

    GEMM_MAINLOOP(A, B, TT)

    #pragma unroll
    for (int mt = 0; mt < 4; mt++) {
        const size_t t0 = m0 + wm + mt * 16 + g;    // time index
        const size_t t1 = t0 + 8;
        #pragma unroll
        for (int nt = 0; nt < 8; nt++) {
            const int colpair = (int)((n0 + wn + nt * 8) >> 1) + tg;  // = b*1024 + d
            const int b = colpair >> 10, d = colpair & 1023;
            const size_t mrow0 = t0 * BB + b;
            const size_t mrow1 = t1 * BB + b;
            float q0 = __half2float(qx[mrow0 * DD + d]);
            float q1 = __half2float(qx[mrow1 * DD + d]);
            float s0 = 1.0f / (1.0f + expf(-q0));
            float s1 = 1.0f / (1.0f + expf(-q1));
            ag[mrow0 * (2 * DD) + d] =
                __float2half_rn(s0 * (c[mt][nt][0] / c[mt][nt][1]));
            ag[mrow1 * (2 * DD) + d] =
                __float2half_rn(s1 * (c[mt][nt][2] / c[mt][nt][3]));
        }
    }
}

// Final GEMM: out = data + ag @ w34^T + b34
__global__ void __launch_bounds__(NTHREADS, 2) gemm_out(
    const __half* __restrict__ A, const __half* __restrict__ B,
    const float* __restrict__ bias, const float* __restrict__ aux,
    float* __restrict__ C)
{
    extern __shared__ __half sm[];
    const uint32_t smBase = (uint32_t)__cvta_generic_to_shared(sm);
    const int tid = threadIdx.x;
    const size_t m0 = (size_t)blockIdx.y * BM;
    const size_t n0 = (size_t)blockIdx.x * BN;
    const int warp = tid >> 5, lane = tid & 31;
    const int g = lane >> 2, tg = lane & 3;
    const int wm = (warp >> 1) * 64;
    const int wn = (warp & 1) * 64;
    const int N = DD;

    float c[4][8][4];
    #pragma unroll
    for (int i = 0; i < 4; i++)
        #pragma unroll
        for (int j = 0; j < 8; j++)
            #pragma unroll
            for (int e = 0; e < 4; e++) c[i][j][e] = 0.0f;

    GEMM_MAINLOOP(A, B, 2 * DD)

    #pragma unroll
    for (int mt = 0; mt < 4; mt++) {
        const size_t r0 = m0 + wm + mt * 16 + g;
        const size_t r1 = r0 + 8;
        #pragma unroll
        for (int nt = 0; nt < 8; nt++) {
            const size_t col = n0 + wn + nt * 8 + tg * 2;
            const float b0 = bias[col], b1 = bias[col + 1];
            const size_t i0 = r0 * N + col;
            const size_t i1 = r1 * N + col;
            C[i0]     = c[mt][nt][0] + b0 + aux[i0];
            C[i0 + 1] = c[mt][nt][1] + b1 + aux[i0 + 1];
            C[i1]     = c[mt][nt][2] + b0 + aux[i1];
            C[i1 + 1] = c[mt][nt][3] + b1 + aux[i1 + 1];
        }
    }
}

// ---------------------------------------------------------------------------
// Host launch
// ---------------------------------------------------------------------------
extern "C" void kernel_launch(void* const* d_in, const int* in_sizes, int n_in,
                              void* d_out, int out_size) {
    const float* data  = (const float*)d_in[0];
    const float* qkv_w = (const float*)d_in[1];
    const float* qkv_b = (const float*)d_in[2];
    const float* pos_b = (const float*)d_in[3];
    const float* out_w = (const float*)d_in[4];
    const float* out_b = (const float*)d_in[5];
    const float* fc1_w = (const float*)d_in[6];
    const float* fc1_b = (const float*)d_in[7];
    const float* fc2_w = (const float*)d_in[8];
    const float* fc2_b = (const float*)d_in[9];
    float* out = (float*)d_out;

    __half *h, *qx, *W, *XT, *ag, *w12, *w34;
    float *b12, *b34;
    cudaGetSymbolAddress((void**)&h,   g_h);
    cudaGetSymbolAddress((void**)&qx,  g_qx);
    cudaGetSymbolAddress((void**)&W,   g_W);
    cudaGetSymbolAddress((void**)&XT,  g_XT);
    cudaGetSymbolAddress((void**)&ag,  g_ag);
    cudaGetSymbolAddress((void**)&w12, g_w12);
    cudaGetSymbolAddress((void**)&w34, g_w34);
    cudaGetSymbolAddress((void**)&b12, g_b12);
    cudaGetSymbolAddress((void**)&b34, g_b34);

    cudaFuncSetAttribute(gemm_qkv, cudaFuncAttributeMaxDynamicSharedMemorySize, SMEM_BYTES);
    cudaFuncSetAttribute(gemm_aft, cudaFuncAttributeMaxDynamicSharedMemorySize, SMEM_BYTES);
    cudaFuncSetAttribute(gemm_out, cudaFuncAttributeMaxDynamicSharedMemorySize, SMEM_BYTES);

    // fused layernorm + weight/bias/exp(pos_bias) prep (one launch)
    lnprep_k<<<MROWS + P5_END / 256, 256>>>(data, h,
                                            qkv_w, fc1_w, out_w, fc2_w,
                                            qkv_b, fc1_b, out_b, fc2_b, pos_b,
                                            w12, w34, W, b12, b34);

    // projection GEMM: q -> qx; (k,v) -> exp/transpose -> XT; (x1,gate) -> SwiGLU -> ag
    gemm_qkv<<<dim3(5*DD/BN, MROWS/BM), NTHREADS, SMEM_BYTES>>>(h, w12, b12, qx, XT, ag);

    // act half of ag: fused W@XT^T + sigmoid(q)*num/den  (grid: x=m, y=n)
    gemm_aft<<<dim3(TT/BM, 2*BB*DD/BN), NTHREADS, SMEM_BYTES>>>(W, XT, qx, ag);

    // out = data + ag @ w34^T + b34   (fused out-proj + fc2)
    gemm_out<<<dim3(DD/BN, MROWS/BM), NTHREADS, SMEM_BYTES>>>(ag, w34, b34, data, out);
}

// round 17
// speedup vs baseline: 1.2030x; 1.0207x over previous
#include <cuda_runtime.h>
#include <cuda_fp16.h>
#include <cstdint>
#include <cstdio>

// Problem dims (fixed): T=2048, B=8, D=1024
#define TT 2048
#define BB 8
#define DD 1024
#define MROWS (TT*BB)          // 16384

// ---------------------------------------------------------------------------
// Scratch (device globals; no allocation allowed)
// ---------------------------------------------------------------------------
__device__ __half g_h  [(size_t)MROWS * DD];          // layernorm(data), fp16
__device__ __half g_qx [(size_t)MROWS * DD];          // q only, fp16
__device__ __half g_W  [(size_t)TT * TT];             // exp(pos_bias), fp16
__device__ __half g_XT [(size_t)2 * BB * DD * TT];    // row 2n = ek*v, 2n+1 = ek (n=b*D+d)
__device__ __half g_ag [(size_t)MROWS * 2 * DD];      // [act | gate-ffn] per row (K=2048)
__device__ __half g_w12[(size_t)5*DD*DD];             // [q ; interleaved k/v ; interleaved x1/gate]
__device__ __half g_w34[(size_t)DD*2*DD];             // row n = [out_w[n] | fc2_w[n]]
__device__ float  g_b12[(size_t)5*DD];                // matching interleaved biases
__device__ float  g_b34[(size_t)DD];

// ---------------------------------------------------------------------------
// Helpers
// ---------------------------------------------------------------------------
__device__ __forceinline__ void cp_async16(uint32_t saddr, const void* gptr) {
    asm volatile("cp.async.cg.shared.global [%0], [%1], 16;\n" :: "r"(saddr), "l"(gptr));
}
__device__ __forceinline__ void cp_commit() {
    asm volatile("cp.async.commit_group;\n");
}
__device__ __forceinline__ void ldsm_x4(uint32_t& r0, uint32_t& r1, uint32_t& r2, uint32_t& r3,
                                        uint32_t addr) {
    asm volatile("ldmatrix.sync.aligned.m8n8.x4.shared.b16 {%0,%1,%2,%3}, [%4];"
                 : "=r"(r0), "=r"(r1), "=r"(r2), "=r"(r3) : "r"(addr));
}

// ---------------------------------------------------------------------------
// Fused layernorm + prep kernel (block-range dispatch).
// ---------------------------------------------------------------------------
#define P0_END (DD*DD)                   // w12 q rows (straight copy)
#define P1_END (P0_END + DD*DD)          // w12 k/v interleave
#define P2_END (P1_END + DD*DD)          // w12 x1/gate interleave
#define P3_END (P2_END + DD*DD)          // w34
#define P4_END (P3_END + TT*TT)          // expw
#define P5_END (P4_END + 4096)           // biases

__global__ void lnprep_k(const float* __restrict__ data, __half* __restrict__ h,
                         const float* __restrict__ qkv_w, const float* __restrict__ fc1_w,
                         const float* __restrict__ out_w, const float* __restrict__ fc2_w,
                         const float* __restrict__ qkv_b, const float* __restrict__ fc1_b,
                         const float* __restrict__ out_b, const float* __restrict__ fc2_b,
                         const float* __restrict__ pos_b,
                         __half* __restrict__ w12, __half* __restrict__ w34,
                         __half* __restrict__ W,
                         float* __restrict__ b12, float* __restrict__ b34) {
    if (blockIdx.x < MROWS) {
        __shared__ float red[16];
        const size_t row = blockIdx.x;
        const float4* xr = (const float4*)(data + row * DD);
        float4 v = xr[threadIdx.x];
        float s = v.x + v.y + v.z + v.w;
        float q = v.x*v.x + v.y*v.y + v.z*v.z + v.w*v.w;
        #pragma unroll
        for (int o = 16; o; o >>= 1) {
            s += __shfl_xor_sync(0xffffffffu, s, o);
            q += __shfl_xor_sync(0xffffffffu, q, o);
        }
        int wid = threadIdx.x >> 5;
        if ((threadIdx.x & 31) == 0) { red[wid] = s; red[8 + wid] = q; }
        __syncthreads();
        s = 0.f; q = 0.f;
        #pragma unroll
        for (int i = 0; i < 8; i++) { s += red[i]; q += red[8 + i]; }
        float mean = s * (1.0f / DD);
        float var  = fmaxf(q * (1.0f / DD) - mean * mean, 0.0f);
        float rs   = rsqrtf(var + 1.17549435e-38f);
        __half2* hr = (__half2*)(h + row * DD);
        hr[2*threadIdx.x]     = __floats2half2_rn((v.x - mean) * rs, (v.y - mean) * rs);
        hr[2*threadIdx.x + 1] = __floats2half2_rn((v.z - mean) * rs, (v.w - mean) * rs);
        return;
    }
    int i = (blockIdx.x - MROWS) * blockDim.x + threadIdx.x;
    if (i < P0_END) {
        w12[i] = __float2half_rn(qkv_w[i]);
    } else if (i < P1_END) {
        int i2 = i - P0_END;
        int d = i2 >> 10, c = i2 & 1023;
        size_t base = ((size_t)DD + 2 * d) * DD;
        w12[base + c]      = __float2half_rn(qkv_w[(size_t)(DD + d) * DD + c]);     // k_d
        w12[base + DD + c] = __float2half_rn(qkv_w[(size_t)(2 * DD + d) * DD + c]); // v_d
    } else if (i < P2_END) {
        int i2 = i - P1_END;
        int d = i2 >> 10, c = i2 & 1023;
        size_t base = ((size_t)3 * DD + 2 * d) * DD;
        w12[base + c]      = __float2half_rn(fc1_w[(size_t)d * DD + c]);            // x1_d
        w12[base + DD + c] = __float2half_rn(fc1_w[(size_t)(DD + d) * DD + c]);     // gate_d
    } else if (i < P3_END) {
        int i2 = i - P2_END;
        int n = i2 >> 10, c = i2 & 1023;
        w34[(size_t)n * 2048 + c]        = __float2half_rn(out_w[i2]);
        w34[(size_t)n * 2048 + 1024 + c] = __float2half_rn(fc2_w[i2]);
    } else if (i < P4_END) {
        int i2 = i - P3_END;
        W[i2] = __float2half_rn(expf(pos_b[i2]));
    } else if (i < P5_END) {
        int i2 = i - P4_END;
        if (i2 < DD) {
            b12[i2] = qkv_b[i2];
            b34[i2] = out_b[i2] + fc2_b[i2];
        } else if (i2 < 2 * DD) {
            int d = i2 - DD;
            b12[DD + 2 * d]     = qkv_b[DD + d];
            b12[DD + 2 * d + 1] = qkv_b[2 * DD + d];
        } else if (i2 < 3 * DD) {
            int d = i2 - 2 * DD;
            b12[3 * DD + 2 * d]     = fc1_b[d];
            b12[3 * DD + 2 * d + 1] = fc1_b[DD + d];
        }
    }
}

// ---------------------------------------------------------------------------
// GEMM tile config
// fp16 mma.sync m16n8k16 (fp32 accum), 128x128x64 block tile, 4 warps (2x2 of
// 64x64 warp tiles, 128 threads), cp.async 3-stage smem pipeline + 2-deep
// register fragment pipeline, XOR-swizzled smem rows (128 B). 2 CTAs/SM.
// ---------------------------------------------------------------------------
#define BM 128
#define BN 128
#define BK 64                                   // halves per k-tile
#define NTHREADS 128
#define STAGES 3
#define A_TILE_BYTES 16384                      // 128 rows * 128 B
#define STAGE_BYTES  32768                      // A + B
#define SMEM_BYTES (STAGES * STAGE_BYTES)       // 98,304 B

// fragment load macros (af[2][4][4], bf[2][8][2] must be in scope)
#define LOAD_FRAGS(buf, ksv)                                                          \
    {                                                                                 \
        const uint32_t swA = ((chA + 2 * (ksv)) ^ rm) << 4;                           \
        const uint32_t swB = ((chB + 2 * (ksv)) ^ rm) << 4;                           \
        _Pragma("unroll")                                                             \
        for (int mt = 0; mt < 4; mt++)                                                \
            ldsm_x4(af[buf][mt][0], af[buf][mt][1], af[buf][mt][2], af[buf][mt][3],   \
                    aTile + aOff[mt] + swA);                                          \
        _Pragma("unroll")                                                             \
        for (int p = 0; p < 4; p++)                                                   \
            ldsm_x4(bf[buf][2*p][0], bf[buf][2*p][1],                                 \
                    bf[buf][2*p+1][0], bf[buf][2*p+1][1],                             \
                    bTile + bOff[p] + swB);                                           \
    }

// Mainloop shared by all GEMMs (accumulates c[4][8][4])
#define GEMM_MAINLOOP(Aptr, Bptr, Kdim)                                              \
    const int lr = tid >> 3;                                                          \
    const int lc = tid & 7;                                                           \
    const int scw = lc ^ (lr & 7);                                                    \
    const __half* gA = (Aptr) + (m0 + lr) * (size_t)(Kdim) + lc * 8;                  \
    const __half* gB = (Bptr) + (n0 + lr) * (size_t)(Kdim) + lc * 8;                  \
    const uint32_t sAa = smBase + (lr * 64 + scw * 8) * 2;                            \
    const uint32_t sBa = sAa + A_TILE_BYTES;                                          \
    const uint32_t rm  = lane & 7;                                                    \
    const uint32_t chA = lane >> 4;                                                   \
    const uint32_t chB = (lane >> 3) & 1;                                             \
    uint32_t aOff[4], bOff[4];                                                        \
    _Pragma("unroll")                                                                 \
    for (int mt = 0; mt < 4; mt++)                                                    \
        aOff[mt] = (wm + mt * 16 + (lane & 15)) * 128;                                \
    _Pragma("unroll")                                                                 \
    for (int p = 0; p < 4; p++)                                                       \
        bOff[p] = (wn + 16 * p + 8 * (lane >> 4) + (lane & 7)) * 128;                 \
    const int nk = (Kdim) / BK;                                                       \
    _Pragma("unroll")                                                                 \
    for (int st = 0; st < STAGES - 1; st++) {                                         \
        const uint32_t da = sAa + st * STAGE_BYTES;                                   \
        const uint32_t db = sBa + st * STAGE_BYTES;                                   \
        const size_t ko = (size_t)st * BK;                                            \
        _Pragma("unroll")                                                             \
        for (int i = 0; i < 8; i++) {                                                 \
            cp_async16(da + i * 2048, gA + ko + (size_t)(16 * i) * (Kdim));           \
            cp_async16(db + i * 2048, gB + ko + (size_t)(16 * i) * (Kdim));           \
        }                                                                             \
        cp_commit();                                                                  \
    }                                                                                 \
    int slot = 0, wslot = STAGES - 1;                                                 \
    uint32_t af[2][4][4], bf[2][8][2];                                                \
    for (int kt = 0; kt < nk; kt++) {                                                 \
        asm volatile("cp.async.wait_group %0;\n" :: "n"(STAGES - 2) : "memory");      \
        __syncthreads();                                                              \
        const uint32_t aTile = smBase + slot * STAGE_BYTES;                           \
        const uint32_t bTile = aTile + A_TILE_BYTES;                                  \
        LOAD_FRAGS(0, 0)                                                              \
        if (kt + STAGES - 1 < nk) {                                                   \
            const uint32_t da = sAa + wslot * STAGE_BYTES;                            \
            const uint32_t db = sBa + wslot * STAGE_BYTES;                            \
            const size_t ko = (size_t)(kt + STAGES - 1) * BK;                         \
            _Pragma("unroll")                                                         \
            for (int i = 0; i < 8; i++) {                                             \
                cp_async16(da + i * 2048, gA + ko + (size_t)(16 * i) * (Kdim));       \
                cp_async16(db + i * 2048, gB + ko + (size_t)(16 * i) * (Kdim));       \
            }                                                                         \
        }                                                                             \
        cp_commit();                                                                  \
        _Pragma("unroll")                                                             \
        for (int ks = 0; ks < 4; ks++) {                                              \
            const int cb = ks & 1;                                                    \
            if (ks < 3) LOAD_FRAGS(cb ^ 1, ks + 1)                                    \
            _Pragma("unroll")                                                         \
            for (int mt = 0; mt < 4; mt++)                                            \
                _Pragma("unroll")                                                     \
                for (int nt = 0; nt < 8; nt++) {                                      \
                    asm volatile(                                                     \
                        "mma.sync.aligned.m16n8k16.row.col.f32.f16.f16.f32 "          \
                        "{%0,%1,%2,%3}, {%4,%5,%6,%7}, {%8,%9}, {%0,%1,%2,%3};\n"     \
                        : "+f"(c[mt][nt][0]), "+f"(c[mt][nt][1]),                     \
                          "+f"(c[mt][nt][2]), "+f"(c[mt][nt][3])                      \
                        : "r"(af[cb][mt][0]), "r"(af[cb][mt][1]),                     \
                          "r"(af[cb][mt][2]), "r"(af[cb][mt][3]),                     \
                          "r"(bf[cb][nt][0]), "r"(bf[cb][nt][1]));                    \
                }                                                                     \
        }                                                                             \
        slot  = (slot  == STAGES - 1) ? 0 : slot + 1;                                 \
        wslot = (wslot == STAGES - 1) ? 0 : wslot + 1;                                \
    }

// Projection GEMM: A = h [16384,1024], B = w12 [5120,1024].
//  n0 <  1024: qx = q (+bias)
//  n0 <  3072: interleaved (k,v) pairs -> fused exp + smem transpose -> XT
//  else      : interleaved (x1,gate)   -> fused SwiGLU -> ag[:,1024:2048]
__global__ void __launch_bounds__(NTHREADS, 2) gemm_qkv(
    const __half* __restrict__ A, const __half* __restrict__ B,
    const float* __restrict__ bias,
    __half* __restrict__ qx, __half* __restrict__ XT, __half* __restrict__ ag)
{
    extern __shared__ __half sm[];
    const uint32_t smBase = (uint32_t)__cvta_generic_to_shared(sm);
    const int tid = threadIdx.x;
    const size_t m0 = (size_t)blockIdx.y * BM;
    const size_t n0 = (size_t)blockIdx.x * BN;
    const int warp = tid >> 5, lane = tid & 31;
    const int g = lane >> 2, tg = lane & 3;
    const int wm = (warp >> 1) * 64;
    const int wn = (warp & 1) * 64;

    float c[4][8][4];
    #pragma unroll
    for (int i = 0; i < 4; i++)
        #pragma unroll
        for (int j = 0; j < 8; j++)
            #pragma unroll
            for (int e = 0; e < 4; e++) c[i][j][e] = 0.0f;

    GEMM_MAINLOOP(A, B, DD)

    if (n0 < DD) {
        // ---- q epilogue -> qx [MROWS, DD] ----
        #pragma unroll
        for (int mt = 0; mt < 4; mt++) {
            const size_t r0 = m0 + wm + mt * 16 + g;
            const size_t r1 = r0 + 8;
            #pragma unroll
            for (int nt = 0; nt < 8; nt++) {
                const size_t col = n0 + wn + nt * 8 + tg * 2;
                const float b0 = bias[col], b1 = bias[col + 1];
                *(__half2*)(qx + r0 * DD + col) =
                    __floats2half2_rn(c[mt][nt][0] + b0, c[mt][nt][1] + b1);
                *(__half2*)(qx + r1 * DD + col) =
                    __floats2half2_rn(c[mt][nt][2] + b0, c[mt][nt][3] + b1);
            }
        }
    } else if (n0 < 3 * DD) {
        // ---- k/v epilogue: exp + transpose -> XT ----
        // CTA covers t in [t0, t0+16), all 8 b, d in [d0, d0+64).
        __syncthreads();   // stage buffers dead; reuse smem for transpose
        __half* sekv = sm;                 // 512 chunks * 16 halves = 16 KB
        __half* sek  = sm + 8192;          // another 16 KB
        #pragma unroll
        for (int nt = 0; nt < 8; nt++) {
            const int collocal = wn + nt * 8 + tg * 2;
            const int dl = collocal >> 1;
            const size_t col = n0 + collocal;
            const float bk = bias[col], bv = bias[col + 1];
            uint32_t pkv[4], pke[4];
            #pragma unroll
            for (int mt = 0; mt < 4; mt++) {
                float k0 = c[mt][nt][0] + bk, v0 = c[mt][nt][1] + bv;
                float k1 = c[mt][nt][2] + bk, v1 = c[mt][nt][3] + bv;
                float e0 = expf(k0), e1 = expf(k1);
                __half2 hv = __floats2half2_rn(e0 * v0, e1 * v1);
                __half2 he = __floats2half2_rn(e0, e1);
                pkv[mt] = *(uint32_t*)&hv;
                pke[mt] = *(uint32_t*)&he;
            }
            const int chunk = dl * 8 + g;           // b = g
            const int toff  = (wm >> 3);            // 0 or 8
            *(uint4*)(sekv + chunk * 16 + toff) = make_uint4(pkv[0], pkv[1], pkv[2], pkv[3]);
            *(uint4*)(sek  + chunk * 16 + toff) = make_uint4(pke[0], pke[1], pke[2], pke[3]);
        }
        __syncthreads();
        const int t0 = (int)(m0 >> 3);
        const int d0 = (int)((n0 - DD) >> 1);
        #pragma unroll
        for (int i = 0; i < 8; i++) {
            const int cid = tid + NTHREADS * i;     // [0, 1024)
            const int s = cid >> 9;                 // 0 = ekv, 1 = ek
            const int rowid = cid & 511;            // = dl*8 + b
            const int dl = rowid >> 3, b = rowid & 7;
            const __half* src = (s ? sek : sekv) + rowid * 16;
            const size_t xrow = 2 * ((size_t)b * DD + d0 + dl) + s;
            uint4* dst = (uint4*)(XT + xrow * TT + t0);
            dst[0] = ((const uint4*)src)[0];
            dst[1] = ((const uint4*)src)[1];
        }
    } else {
        // ---- fused SwiGLU epilogue -> ag[:, 1024 + d] ----
        #pragma unroll
        for (int mt = 0; mt < 4; mt++) {
            const size_t r0 = m0 + wm + mt * 16 + g;
            const size_t r1 = r0 + 8;
            #pragma unroll
            for (int nt = 0; nt < 8; nt++) {
                const size_t col = n0 + wn + nt * 8 + tg * 2;
                const float b0 = bias[col], b1 = bias[col + 1];
                const int d = (int)((col - 3 * DD) >> 1);
                float x1a = c[mt][nt][0] + b0, gta = c[mt][nt][1] + b1;
                float x1b = c[mt][nt][2] + b0, gtb = c[mt][nt][3] + b1;
                float spa = (gta > 20.0f) ? gta : log1pf(expf(gta));
                float spb = (gtb > 20.0f) ? gtb : log1pf(expf(gtb));
                ag[r0 * (2 * DD) + DD + d] = __float2half_rn(x1a * gta * tanhf(spa));
                ag[r1 * (2 * DD) + DD + d] = __float2half_rn(x1b * gtb * tanhf(spb));
            }
        }
    }
}

// Y-GEMM with fused AFT activation epilogue.
// A = W [T,T], B = XT [16384, T] (row 2n = ekv, 2n+1 = ek).
// Grid: x = m (16), y = n (128).
__global__ void __launch_bounds__(NTHREADS, 2) gemm_aft(
    const __half* __restrict__ A, const __half* __restrict__ B,
    const __half* __restrict__ qx, __half* __restrict__ ag)
{
    extern __shared__ __half sm[];
    const uint32_t smBase = (uint32_t)__cvta_generic_to_shared(sm);
    const int tid = threadIdx.x;
    const size_t m0 = (size_t)blockIdx.x * BM;
    const size_t n0 = (size_t)blockIdx.y * BN;
    const int warp = tid >> 5, lane = tid & 31;
    const int g = lane >> 2, tg = lane & 3;
    const int wm = (warp >> 1) * 64;
    const int wn = (warp & 1) * 64;

    float c[4][8][4];
    #pragma unroll
    for (int i = 0; i < 4; i++)
        #pragma unroll
        for (int j = 0; j < 8; j++)
            #pragma unroll
            for (int e = 0; e < 4; e++) c[i][j][e] = 0.0f;

    GEMM_MAINLOOP(A, B, TT)

    #pragma unroll
    for (int mt = 0; mt < 4; mt++) {
        const size_t t0 = m0 + wm + mt * 16 + g;    // time index
        const size_t t1 = t0 + 8;
        #pragma unroll
        for (int nt = 0; nt < 8; nt++) {
            const int colpair = (int)((n0 + wn + nt * 8) >> 1) + tg;  // = b*1024 + d
            const int b = colpair >> 10, d = colpair & 1023;
            const size_t mrow0 = t0 * BB + b;
            const size_t mrow1 = t1 * BB + b;
            float q0 = __half2float(qx[mrow0 * DD + d]);
            float q1 = __half2float(qx[mrow1 * DD + d]);
            float s0 = 1.0f / (1.0f + expf(-q0));
            float s1 = 1.0f / (1.0f + expf(-q1));
            ag[mrow0 * (2 * DD) + d] =
                __float2half_rn(s0 * (c[mt][nt][0] / c[mt][nt][1]));
            ag[mrow1 * (2 * DD) + d] =
                __float2half_rn(s1 * (c[mt][nt][2] / c[mt][nt][3]));
        }
    }
}

// Final GEMM: out = data + ag @ w34^T + b34
__global__ void __launch_bounds__(NTHREADS, 2) gemm_out(
    const __half* __restrict__ A, const __half* __restrict__ B,
    const float* __restrict__ bias, const float* __restrict__ aux,
    float* __restrict__ C)
{
    extern __shared__ __half sm[];
    const uint32_t smBase = (uint32_t)__cvta_generic_to_shared(sm);
    const int tid = threadIdx.x;
    const size_t m0 = (size_t)blockIdx.y * BM;
    const size_t n0 = (size_t)blockIdx.x * BN;
    const int warp = tid >> 5, lane = tid & 31;
    const int g = lane >> 2, tg = lane & 3;
    const int wm = (warp >> 1) * 64;
    const int wn = (warp & 1) * 64;
    const int N = DD;

    float c[4][8][4];
    #pragma unroll
    for (int i = 0; i < 4; i++)
        #pragma unroll
        for (int j = 0; j < 8; j++)
            #pragma unroll
            for (int e = 0; e < 4; e++) c[i][j][e] = 0.0f;

    GEMM_MAINLOOP(A, B, 2 * DD)

    #pragma unroll
    for (int mt = 0; mt < 4; mt++) {
        const size_t r0 = m0 + wm + mt * 16 + g;
        const size_t r1 = r0 + 8;
        #pragma unroll
        for (int nt = 0; nt < 8; nt++) {
            const size_t col = n0 + wn + nt * 8 + tg * 2;
            const float b0 = bias[col], b1 = bias[col + 1];
            const size_t i0 = r0 * N + col;
            const size_t i1 = r1 * N + col;
            C[i0]     = c[mt][nt][0] + b0 + aux[i0];
            C[i0 + 1] = c[mt][nt][1] + b1 + aux[i0 + 1];
            C[i1]     = c[mt][nt][2] + b0 + aux[i1];
            C[i1 + 1] = c[mt][nt][3] + b1 + aux[i1 + 1];
        }
    }
}

// ---------------------------------------------------------------------------
// Host launch
// ---------------------------------------------------------------------------
extern "C" void kernel_launch(void* const* d_in, const int* in_sizes, int n_in,
                              void* d_out, int out_size) {
    const float* data  = (const float*)d_in[0];
    const float* qkv_w = (const float*)d_in[1];
    const float* qkv_b = (const float*)d_in[2];
    const float* pos_b = (const float*)d_in[3];
    const float* out_w = (const float*)d_in[4];
    const float* out_b = (const float*)d_in[5];
    const float* fc1_w = (const float*)d_in[6];
    const float* fc1_b = (const float*)d_in[7];
    const float* fc2_w = (const float*)d_in[8];
    const float* fc2_b = (const float*)d_in[9];
    float* out = (float*)d_out;

    __half *h, *qx, *W, *XT, *ag, *w12, *w34;
    float *b12, *b34;
    cudaGetSymbolAddress((void**)&h,   g_h);
    cudaGetSymbolAddress((void**)&qx,  g_qx);
    cudaGetSymbolAddress((void**)&W,   g_W);
    cudaGetSymbolAddress((void**)&XT,  g_XT);
    cudaGetSymbolAddress((void**)&ag,  g_ag);
    cudaGetSymbolAddress((void**)&w12, g_w12);
    cudaGetSymbolAddress((void**)&w34, g_w34);
    cudaGetSymbolAddress((void**)&b12, g_b12);
    cudaGetSymbolAddress((void**)&b34, g_b34);

    cudaFuncSetAttribute(gemm_qkv, cudaFuncAttributeMaxDynamicSharedMemorySize, SMEM_BYTES);
    cudaFuncSetAttribute(gemm_aft, cudaFuncAttributeMaxDynamicSharedMemorySize, SMEM_BYTES);
    cudaFuncSetAttribute(gemm_out, cudaFuncAttributeMaxDynamicSharedMemorySize, SMEM_BYTES);

    // fused layernorm + weight/bias/exp(pos_bias) prep (one launch)
    lnprep_k<<<MROWS + P5_END / 256, 256>>>(data, h,
                                            qkv_w, fc1_w, out_w, fc2_w,
                                            qkv_b, fc1_b, out_b, fc2_b, pos_b,
                                            w12, w34, W, b12, b34);

    // projection GEMM: q -> qx; (k,v) -> exp/transpose -> XT; (x1,gate) -> SwiGLU -> ag
    gemm_qkv<<<dim3(5*DD/BN, MROWS/BM), NTHREADS, SMEM_BYTES>>>(h, w12, b12, qx, XT, ag);

    // act half of ag: fused W@XT^T + sigmoid(q)*num/den  (grid: x=m, y=n)
    gemm_aft<<<dim3(TT/BM, 2*BB*DD/BN), NTHREADS, SMEM_BYTES>>>(W, XT, qx, ag);

    // out = data + ag @ w34^T + b34   (fused out-proj + fc2)
    gemm_out<<<dim3(DD/BN, MROWS/BM), NTHREADS, SMEM_BYTES>>>(ag, w34, b34, data, out);
}